// round 9
// baseline (speedup 1.0000x reference)
#include <cuda_runtime.h>
#include <cuda_bf16.h>

#define NC   2048
#define RESH 16
#define RESW 16
#define NF   64
#define NP   256                  // samples per complex
#define TILE_FLOATS (RESH * RESW * NF)   // 16384 floats = 64 KB
#define TILE_F4     (TILE_FLOATS / 4)    // 4096 float4
#define ITERS (NP / 16)           // 16 samples per thread-group slot

__global__ __launch_bounds__(256, 3)
void ngf_fetch_kernel(const float* __restrict__ map,
                      const float* __restrict__ u,
                      const float* __restrict__ v,
                      float* __restrict__ out)
{
    extern __shared__ float tile[];   // [16*16*64] row-major (y, x, f)

    const int c   = blockIdx.x;
    const int tid = threadIdx.x;
    const int lane16 = tid & 15;      // feature chunk (4 floats)
    const int grp    = tid >> 4;      // sample group 0..15

    const float* uc = u + (size_t)c * NP;
    const float* vc = v + (size_t)c * NP;

    // ---- Prefetch this thread's 16 u/v pairs (independent of smem) ----
    float uu[ITERS], vv[ITERS];
    #pragma unroll
    for (int it = 0; it < ITERS; ++it) {
        uu[it] = __ldg(uc + grp + it * 16);
        vv[it] = __ldg(vc + grp + it * 16);
    }

    // ---- Stage the 64 KB map tile into shared memory (float4, coalesced) ----
    {
        const float4* src = reinterpret_cast<const float4*>(map + (size_t)c * TILE_FLOATS);
        float4* dst = reinterpret_cast<float4*>(tile);
        #pragma unroll
        for (int i = 0; i < TILE_F4 / 256; ++i) {
            dst[tid + i * 256] = src[tid + i * 256];
        }
    }
    __syncthreads();

    float4* outc = reinterpret_cast<float4*>(out + (size_t)c * NP * NF);

    #pragma unroll 4
    for (int it = 0; it < ITERS; ++it) {
        const int p = grp + it * 16;

        const float x = uu[it] * (float)(RESW - 1);
        const float y = vv[it] * (float)(RESH - 1);

        int x0 = (int)floorf(x);
        int y0 = (int)floorf(y);
        x0 = max(0, min(x0, RESW - 2));
        y0 = max(0, min(y0, RESH - 2));

        const float fx = x - (float)x0;
        const float fy = y - (float)y0;
        const float w00 = (1.0f - fx) * (1.0f - fy);
        const float w01 = fx * (1.0f - fy);
        const float w10 = (1.0f - fx) * fy;
        const float w11 = fx * fy;

        // base float4 index of texel (y0, x0); lane16 picks the feature chunk
        const float4* base = reinterpret_cast<const float4*>(tile) +
                             (y0 * RESW + x0) * (NF / 4) + lane16;

        const float4 g00 = base[0];
        const float4 g01 = base[NF / 4];              // x0+1  -> +64 floats
        const float4 g10 = base[RESW * NF / 4];       // y0+1  -> +1024 floats
        const float4 g11 = base[RESW * NF / 4 + NF / 4];

        float4 r;
        r.x = g00.x * w00 + g01.x * w01 + g10.x * w10 + g11.x * w11;
        r.y = g00.y * w00 + g01.y * w01 + g10.y * w10 + g11.y * w11;
        r.z = g00.z * w00 + g01.z * w01 + g10.z * w10 + g11.z * w11;
        r.w = g00.w * w00 + g01.w * w01 + g10.w * w10 + g11.w * w11;

        // Streaming store: output is write-once, keep it out of L2's way.
        __stcg(&outc[p * (NF / 4) + lane16], r);
    }
}

extern "C" void kernel_launch(void* const* d_in, const int* in_sizes, int n_in,
                              void* d_out, int out_size)
{
    const float* map = (const float*)d_in[0];
    const float* u   = (const float*)d_in[1];
    const float* v   = (const float*)d_in[2];
    float* out = (float*)d_out;

    const int smem = TILE_FLOATS * sizeof(float);   // 64 KB
    cudaFuncSetAttribute(ngf_fetch_kernel,
                         cudaFuncAttributeMaxDynamicSharedMemorySize, smem);

    ngf_fetch_kernel<<<NC, 256, smem>>>(map, u, v, out);
}

// round 14
// speedup vs baseline: 1.0402x; 1.0402x over previous
#include <cuda_runtime.h>
#include <cuda_bf16.h>
#include <cstdint>

#define NC   2048
#define RESH 16
#define RESW 16
#define NF   64
#define NP   256                  // samples per complex
#define TILE_FLOATS (RESH * RESW * NF)   // 16384 floats = 64 KB
#define TILE_BYTES  (TILE_FLOATS * 4)
#define ITERS (NP / 16)           // 16 samples per thread-group slot

__global__ __launch_bounds__(256, 3)
void ngf_fetch_kernel(const float* __restrict__ map,
                      const float* __restrict__ u,
                      const float* __restrict__ v,
                      float* __restrict__ out)
{
    extern __shared__ __align__(1024) float tile[];   // 64 KB dynamic
    __shared__ __align__(8) unsigned long long mbar;  // completion barrier

    const int c   = blockIdx.x;
    const int tid = threadIdx.x;
    const int lane16 = tid & 15;      // feature chunk (4 floats)
    const int grp    = tid >> 4;      // sample group 0..15

    const uint32_t mbar_sa = (uint32_t)__cvta_generic_to_shared(&mbar);
    const uint32_t tile_sa = (uint32_t)__cvta_generic_to_shared(tile);

    // ---- Init mbarrier, then kick one bulk async copy for the whole tile ----
    if (tid == 0) {
        asm volatile("mbarrier.init.shared.b64 [%0], 1;" :: "r"(mbar_sa) : "memory");
    }
    __syncthreads();
    if (tid == 0) {
        asm volatile("mbarrier.arrive.expect_tx.shared.b64 _, [%0], %1;"
                     :: "r"(mbar_sa), "r"((uint32_t)TILE_BYTES) : "memory");
        const float* src = map + (size_t)c * TILE_FLOATS;
        asm volatile(
            "cp.async.bulk.shared::cta.global.mbarrier::complete_tx::bytes "
            "[%0], [%1], %2, [%3];"
            :: "r"(tile_sa), "l"(src), "r"((uint32_t)TILE_BYTES), "r"(mbar_sa)
            : "memory");
    }

    // ---- Prefetch this thread's 16 u/v pairs while the tile streams in ----
    const float* uc = u + (size_t)c * NP;
    const float* vc = v + (size_t)c * NP;
    float uu[ITERS], vv[ITERS];
    #pragma unroll
    for (int it = 0; it < ITERS; ++it) {
        uu[it] = __ldg(uc + grp + it * 16);
        vv[it] = __ldg(vc + grp + it * 16);
    }

    // ---- Wait for the tile (acquire so LDS after sees the TMA writes) ----
    {
        uint32_t done;
        asm volatile(
            "{\n\t"
            ".reg .pred p;\n\t"
            "WAIT_%=:\n\t"
            "mbarrier.try_wait.parity.acquire.cta.shared::cta.b64 p, [%1], 0;\n\t"
            "selp.b32 %0, 1, 0, p;\n\t"
            "@!p bra WAIT_%=;\n\t"
            "}"
            : "=r"(done) : "r"(mbar_sa) : "memory");
    }

    float4* outc = reinterpret_cast<float4*>(out + (size_t)c * NP * NF);

    #pragma unroll 4
    for (int it = 0; it < ITERS; ++it) {
        const int p = grp + it * 16;

        const float x = uu[it] * (float)(RESW - 1);
        const float y = vv[it] * (float)(RESH - 1);

        int x0 = (int)floorf(x);
        int y0 = (int)floorf(y);
        x0 = max(0, min(x0, RESW - 2));
        y0 = max(0, min(y0, RESH - 2));

        const float fx = x - (float)x0;
        const float fy = y - (float)y0;
        const float w00 = (1.0f - fx) * (1.0f - fy);
        const float w01 = fx * (1.0f - fy);
        const float w10 = (1.0f - fx) * fy;
        const float w11 = fx * fy;

        // base float4 index of texel (y0, x0); lane16 picks the feature chunk
        const float4* base = reinterpret_cast<const float4*>(tile) +
                             (y0 * RESW + x0) * (NF / 4) + lane16;

        const float4 g00 = base[0];
        const float4 g01 = base[NF / 4];              // x0+1  -> +64 floats
        const float4 g10 = base[RESW * NF / 4];       // y0+1  -> +1024 floats
        const float4 g11 = base[RESW * NF / 4 + NF / 4];

        float4 r;
        r.x = g00.x * w00 + g01.x * w01 + g10.x * w10 + g11.x * w11;
        r.y = g00.y * w00 + g01.y * w01 + g10.y * w10 + g11.y * w11;
        r.z = g00.z * w00 + g01.z * w01 + g10.z * w10 + g11.z * w11;
        r.w = g00.w * w00 + g01.w * w01 + g10.w * w10 + g11.w * w11;

        // Streaming store: output is write-once, keep it out of L2's way.
        __stcg(&outc[p * (NF / 4) + lane16], r);
    }
}

extern "C" void kernel_launch(void* const* d_in, const int* in_sizes, int n_in,
                              void* d_out, int out_size)
{
    const float* map = (const float*)d_in[0];
    const float* u   = (const float*)d_in[1];
    const float* v   = (const float*)d_in[2];
    float* out = (float*)d_out;

    const int smem = TILE_BYTES;   // 64 KB dynamic
    cudaFuncSetAttribute(ngf_fetch_kernel,
                         cudaFuncAttributeMaxDynamicSharedMemorySize, smem);

    ngf_fetch_kernel<<<NC, 256, smem>>>(map, u, v, out);
}